// round 3
// baseline (speedup 1.0000x reference)
#include <cuda_runtime.h>
#include <cstdint>

#define B_  256
#define T_  250
#define C_  700
#define H1  1024
#define H2  512
#define O_  35
#define THR 1.0f

// ---------------- device scratch (no allocations allowed) ----------------
__device__ float g_ff[(size_t)T_ * B_ * H1];      // [t][b][h1]  ~262MB
__device__ float g_W1T[C_ * H1];                  // [c][h1]
__device__ float g_WrecT[H1 * H1];                // [i][j]
__device__ float g_W2T[H1 * H2];                  // [i][j]
__device__ float g_v1[B_ * H1], g_a1[B_ * H1];
__device__ float g_s1[2][B_ * H1];                // ping-pong (read by all blocks)
__device__ float g_v2[B_ * H2], g_a2[B_ * H2];
__device__ float g_s2[B_ * H2];                   // element-owned, in-place safe
__device__ float g_vout[B_ * O_], g_osum[B_ * O_];

// ---------------- f32x2 helpers (FFMA2 only reachable via PTX) -----------
__device__ __forceinline__ unsigned long long pack2(float lo, float hi) {
    unsigned long long r;
    asm("mov.b64 %0, {%1, %2};" : "=l"(r) : "f"(lo), "f"(hi));
    return r;
}
__device__ __forceinline__ void fma2(unsigned long long& d,
                                     unsigned long long a, unsigned long long b) {
    asm("fma.rn.f32x2 %0, %1, %2, %0;" : "+l"(d) : "l"(a), "l"(b));
}
__device__ __forceinline__ void unpack2(unsigned long long v, float& lo, float& hi) {
    asm("mov.b64 {%0, %1}, %2;" : "=f"(lo), "=f"(hi) : "l"(v));
}

// ---------------- init: zero all state -----------------------------------
__global__ void init_kernel() {
    int i = blockIdx.x * blockDim.x + threadIdx.x;
    int stride = gridDim.x * blockDim.x;
    for (int k = i; k < B_ * H1; k += stride) {
        g_v1[k] = 0.f; g_a1[k] = 0.f; g_s1[0][k] = 0.f; g_s1[1][k] = 0.f;
    }
    for (int k = i; k < B_ * H2; k += stride) {
        g_v2[k] = 0.f; g_a2[k] = 0.f; g_s2[k] = 0.f;
    }
    for (int k = i; k < B_ * O_; k += stride) {
        g_vout[k] = 0.f; g_osum[k] = 0.f;
    }
}

// ---------------- transpose weights ---------------------------------------
__global__ void prep_kernel(const float* __restrict__ W1,
                            const float* __restrict__ Wrec,
                            const float* __restrict__ W2) {
    int i = blockIdx.x * blockDim.x + threadIdx.x;
    int stride = gridDim.x * blockDim.x;
    for (int k = i; k < C_ * H1; k += stride) {
        int c = k / H1, h = k % H1;
        g_W1T[k] = W1[h * C_ + c];
    }
    for (int k = i; k < H1 * H1; k += stride) {
        int r = k / H1, j = k % H1;
        g_WrecT[k] = Wrec[j * H1 + r];
    }
    for (int k = i; k < H1 * H2; k += stride) {
        int r = k / H2, j = k % H2;
        g_W2T[k] = W2[j * H1 + r];
    }
}

// ---------------- FF GEMM: g_ff[t*B+b][h] = x[b,t,:] . W1[h,:] ------------
// M=64000 (row = t*256+b), N=1024, K=700 (padded to 704), tile 64x64x16,
// 256 threads, 4x4 per thread via f32x2.
__global__ void __launch_bounds__(256) ff_kernel(const float* __restrict__ x) {
    __shared__ float As[64][17];   // [m][k]
    __shared__ float Bs[16][68];   // [k][n]
    int tid = threadIdx.x;
    int tx = tid & 15, ty = tid >> 4;
    int n0 = blockIdx.x * 64;
    int row0 = blockIdx.y * 64;

    unsigned long long acc[4][2];
#pragma unroll
    for (int m = 0; m < 4; ++m) { acc[m][0] = 0ull; acc[m][1] = 0ull; }

    // A-load indices
    int am = tid >> 2;                 // 0..63
    int ak = (tid & 3) << 2;           // 0,4,8,12
    int row = row0 + am;
    int bb = row & 255, tt = row >> 8;
    const float* xr = &x[((size_t)bb * T_ + tt) * C_];
    // B-load indices
    int bk = tid >> 4;                 // 0..15
    int bn = (tid & 15) << 2;

    for (int k0 = 0; k0 < 704; k0 += 16) {
        int kg = k0 + ak;
        float4 av = make_float4(0.f, 0.f, 0.f, 0.f);
        if (kg < C_) av = *(const float4*)&xr[kg];   // C_ % 4 == 0, full or none
        int kgb = k0 + bk;
        float4 bv = make_float4(0.f, 0.f, 0.f, 0.f);
        if (kgb < C_) bv = *(const float4*)&g_W1T[(size_t)kgb * H1 + n0 + bn];

        __syncthreads();
        As[am][ak + 0] = av.x; As[am][ak + 1] = av.y;
        As[am][ak + 2] = av.z; As[am][ak + 3] = av.w;
        *(float4*)&Bs[bk][bn] = bv;
        __syncthreads();

#pragma unroll
        for (int k = 0; k < 16; ++k) {
            unsigned long long b0 = *(const unsigned long long*)&Bs[k][tx * 4];
            unsigned long long b1 = *(const unsigned long long*)&Bs[k][tx * 4 + 2];
#pragma unroll
            for (int mm = 0; mm < 4; ++mm) {
                float a = As[ty * 4 + mm][k];
                unsigned long long ap = pack2(a, a);
                fma2(acc[mm][0], ap, b0);
                fma2(acc[mm][1], ap, b1);
            }
        }
    }
#pragma unroll
    for (int mm = 0; mm < 4; ++mm) {
        size_t rbase = (size_t)(row0 + ty * 4 + mm) * H1 + n0 + tx * 4;
        float v0, v1, v2, v3;
        unpack2(acc[mm][0], v0, v1);
        unpack2(acc[mm][1], v2, v3);
        g_ff[rbase + 0] = v0; g_ff[rbase + 1] = v1;
        g_ff[rbase + 2] = v2; g_ff[rbase + 3] = v3;
    }
}

// ---------------- step kernel 1: I1 = ff[t] + s1_prev @ WrecT; neuron1 ----
// GEMM: M=256(batch) N=1024 K=1024, tile 32x64x32, 128 threads, 4x4/thread.
// Blocks 0..127: GEMM tiles.  Blocks 128..135: I3/v_out readout for step t-1.
__global__ void __launch_bounds__(128) step1_kernel(
    const float* __restrict__ W3,
    const float* __restrict__ alpha1, const float* __restrict__ rho1,
    const float* __restrict__ ba1, const float* __restrict__ beta_out, int t) {
    int p = t & 1;
    const float* __restrict__ s1prev = g_s1[p];
    float* __restrict__ s1new = g_s1[1 - p];
    int bx = blockIdx.x;

    if (bx < 128) {
        __shared__ float As[32][33];   // [m][k]
        __shared__ float Bs[32][68];   // [k][n]
        int tid = threadIdx.x;
        int tx = tid & 15, ty = tid >> 4;     // ty 0..7
        int m0 = (bx >> 4) * 32;
        int n0 = (bx & 15) * 64;

        unsigned long long acc[4][2];
#pragma unroll
        for (int m = 0; m < 4; ++m) { acc[m][0] = 0ull; acc[m][1] = 0ull; }

        int am = tid >> 2;               // 0..31
        int ak = (tid & 3) << 3;         // 0,8,16,24
        int bk = tid >> 4;               // 0..7
        int bn = (tid & 15) << 2;

        for (int k0 = 0; k0 < H1; k0 += 32) {
            const float4* asrc = (const float4*)&s1prev[(size_t)(m0 + am) * H1 + k0 + ak];
            float4 a0 = asrc[0], a1v = asrc[1];
            float4 bvv[4];
#pragma unroll
            for (int kk = 0; kk < 4; ++kk)
                bvv[kk] = *(const float4*)&g_WrecT[(size_t)(k0 + bk + kk * 8) * H1 + n0 + bn];

            __syncthreads();
            As[am][ak + 0] = a0.x;  As[am][ak + 1] = a0.y;
            As[am][ak + 2] = a0.z;  As[am][ak + 3] = a0.w;
            As[am][ak + 4] = a1v.x; As[am][ak + 5] = a1v.y;
            As[am][ak + 6] = a1v.z; As[am][ak + 7] = a1v.w;
#pragma unroll
            for (int kk = 0; kk < 4; ++kk)
                *(float4*)&Bs[bk + kk * 8][bn] = bvv[kk];
            __syncthreads();

#pragma unroll
            for (int k = 0; k < 32; ++k) {
                unsigned long long b0 = *(const unsigned long long*)&Bs[k][tx * 4];
                unsigned long long b1 = *(const unsigned long long*)&Bs[k][tx * 4 + 2];
#pragma unroll
                for (int mm = 0; mm < 4; ++mm) {
                    float a = As[ty * 4 + mm][k];
                    unsigned long long ap = pack2(a, a);
                    fma2(acc[mm][0], ap, b0);
                    fma2(acc[mm][1], ap, b1);
                }
            }
        }

        size_t ffbase = (size_t)t * B_ * H1;
#pragma unroll
        for (int mm = 0; mm < 4; ++mm) {
            int b = m0 + ty * 4 + mm;
            float s[4];
            unpack2(acc[mm][0], s[0], s[1]);
            unpack2(acc[mm][1], s[2], s[3]);
#pragma unroll
            for (int nn = 0; nn < 4; ++nn) {
                int j = n0 + tx * 4 + nn;
                int idx = b * H1 + j;
                float I1 = g_ff[ffbase + idx] + s[nn];
                float sp = s1prev[idx];
                float v  = g_v1[idx];
                float a  = g_a1[idx];
                float al = alpha1[j];
                float vn = al * (v - sp * THR) + (1.0f - al) * (I1 - a);
                float sn = (vn - THR >= 0.0f) ? 1.0f : 0.0f;
                g_v1[idx]  = vn;
                g_a1[idx]  = rho1[j] * a + ba1[j] * sn;
                s1new[idx] = sn;
            }
        }
    } else {
        // readout for step t-1: I3 = s2 @ W3.T ; v_out, out_sum update
        if (t == 0) return;
        int sb = bx - 128;   // 0..7 -> 32 batches each
        for (int pair = threadIdx.x; pair < 32 * O_; pair += 128) {
            int b = sb * 32 + pair / O_;
            int o = pair % O_;
            const float4* s4 = (const float4*)&g_s2[b * H2];
            const float4* w4 = (const float4*)&W3[o * H2];
            float4 acc4 = make_float4(0.f, 0.f, 0.f, 0.f);
#pragma unroll 4
            for (int k = 0; k < H2 / 4; ++k) {
                float4 sv = s4[k], wv = w4[k];
                acc4.x += sv.x * wv.x; acc4.y += sv.y * wv.y;
                acc4.z += sv.z * wv.z; acc4.w += sv.w * wv.w;
            }
            float I3 = (acc4.x + acc4.y) + (acc4.z + acc4.w);
            float bo = beta_out[o];
            int oi = b * O_ + o;
            float vo = bo * g_vout[oi] + (1.0f - bo) * I3;
            g_vout[oi] = vo;
            g_osum[oi] += vo;
        }
    }
}

// ---------------- step kernel 2: I2 = s1_cur @ W2T; neuron2 ---------------
// M=256, N=512, K=1024, tile 32x64x32, 128 threads. 64 blocks.
__global__ void __launch_bounds__(128) step2_kernel(
    const float* __restrict__ alpha2, const float* __restrict__ rho2,
    const float* __restrict__ ba2, int t) {
    int p = t & 1;
    const float* __restrict__ s1cur = g_s1[1 - p];

    __shared__ float As[32][33];
    __shared__ float Bs[32][68];
    int tid = threadIdx.x;
    int tx = tid & 15, ty = tid >> 4;
    int bx = blockIdx.x;
    int m0 = (bx >> 3) * 32;
    int n0 = (bx & 7) * 64;

    unsigned long long acc[4][2];
#pragma unroll
    for (int m = 0; m < 4; ++m) { acc[m][0] = 0ull; acc[m][1] = 0ull; }

    int am = tid >> 2;
    int ak = (tid & 3) << 3;
    int bk = tid >> 4;
    int bn = (tid & 15) << 2;

    for (int k0 = 0; k0 < H1; k0 += 32) {
        const float4* asrc = (const float4*)&s1cur[(size_t)(m0 + am) * H1 + k0 + ak];
        float4 a0 = asrc[0], a1v = asrc[1];
        float4 bvv[4];
#pragma unroll
        for (int kk = 0; kk < 4; ++kk)
            bvv[kk] = *(const float4*)&g_W2T[(size_t)(k0 + bk + kk * 8) * H2 + n0 + bn];

        __syncthreads();
        As[am][ak + 0] = a0.x;  As[am][ak + 1] = a0.y;
        As[am][ak + 2] = a0.z;  As[am][ak + 3] = a0.w;
        As[am][ak + 4] = a1v.x; As[am][ak + 5] = a1v.y;
        As[am][ak + 6] = a1v.z; As[am][ak + 7] = a1v.w;
#pragma unroll
        for (int kk = 0; kk < 4; ++kk)
            *(float4*)&Bs[bk + kk * 8][bn] = bvv[kk];
        __syncthreads();

#pragma unroll
        for (int k = 0; k < 32; ++k) {
            unsigned long long b0 = *(const unsigned long long*)&Bs[k][tx * 4];
            unsigned long long b1 = *(const unsigned long long*)&Bs[k][tx * 4 + 2];
#pragma unroll
            for (int mm = 0; mm < 4; ++mm) {
                float a = As[ty * 4 + mm][k];
                unsigned long long ap = pack2(a, a);
                fma2(acc[mm][0], ap, b0);
                fma2(acc[mm][1], ap, b1);
            }
        }
    }

#pragma unroll
    for (int mm = 0; mm < 4; ++mm) {
        int b = m0 + ty * 4 + mm;
        float s[4];
        unpack2(acc[mm][0], s[0], s[1]);
        unpack2(acc[mm][1], s[2], s[3]);
#pragma unroll
        for (int nn = 0; nn < 4; ++nn) {
            int j = n0 + tx * 4 + nn;
            int idx = b * H2 + j;
            float I2 = s[nn];
            float sp = g_s2[idx];
            float v  = g_v2[idx];
            float a  = g_a2[idx];
            float al = alpha2[j];
            float vn = al * (v - sp * THR) + (1.0f - al) * (I2 - a);
            float sn = (vn - THR >= 0.0f) ? 1.0f : 0.0f;
            g_v2[idx] = vn;
            g_a2[idx] = rho2[j] * a + ba2[j] * sn;
            g_s2[idx] = sn;
        }
    }
}

// ---------------- final: readout for t=249 + write out --------------------
__global__ void final_kernel(const float* __restrict__ W3,
                             const float* __restrict__ beta_out,
                             float* __restrict__ out) {
    int i = blockIdx.x * blockDim.x + threadIdx.x;
    if (i >= B_ * O_) return;
    int b = i / O_, o = i % O_;
    const float4* s4 = (const float4*)&g_s2[b * H2];
    const float4* w4 = (const float4*)&W3[o * H2];
    float4 acc4 = make_float4(0.f, 0.f, 0.f, 0.f);
#pragma unroll 4
    for (int k = 0; k < H2 / 4; ++k) {
        float4 sv = s4[k], wv = w4[k];
        acc4.x += sv.x * wv.x; acc4.y += sv.y * wv.y;
        acc4.z += sv.z * wv.z; acc4.w += sv.w * wv.w;
    }
    float I3 = (acc4.x + acc4.y) + (acc4.z + acc4.w);
    float bo = beta_out[o];
    float vo = bo * g_vout[i] + (1.0f - bo) * I3;
    out[i] = (g_osum[i] + vo) / (float)T_;
}

// ---------------- launch ---------------------------------------------------
extern "C" void kernel_launch(void* const* d_in, const int* in_sizes, int n_in,
                              void* d_out, int out_size) {
    const float* x      = (const float*)d_in[0];
    const float* W1     = (const float*)d_in[1];
    const float* Wrec   = (const float*)d_in[2];
    const float* W2     = (const float*)d_in[3];
    const float* W3     = (const float*)d_in[4];
    const float* alpha1 = (const float*)d_in[5];
    const float* rho1   = (const float*)d_in[6];
    const float* ba1    = (const float*)d_in[7];
    const float* alpha2 = (const float*)d_in[8];
    const float* rho2   = (const float*)d_in[9];
    const float* ba2    = (const float*)d_in[10];
    const float* bout   = (const float*)d_in[11];
    float* out = (float*)d_out;

    init_kernel<<<1024, 256>>>();
    prep_kernel<<<4096, 256>>>(W1, Wrec, W2);
    ff_kernel<<<dim3(16, 1000), 256>>>(x);

    for (int t = 0; t < T_; ++t) {
        step1_kernel<<<136, 128>>>(W3, alpha1, rho1, ba1, bout, t);
        step2_kernel<<<64, 128>>>(alpha2, rho2, ba2, t);
    }
    final_kernel<<<(B_ * O_ + 127) / 128, 128>>>(W3, bout, out);
}

// round 9
// speedup vs baseline: 1.5241x; 1.5241x over previous
#include <cuda_runtime.h>
#include <cstdint>

typedef unsigned long long ull;

#define B_  256
#define T_  250
#define C_  700
#define H1  1024
#define H2  512
#define O_  35
#define NB  148
#define THR 1.0f

// ---------------- device scratch (no allocations allowed) ----------------
__device__ float g_ff[(size_t)T_ * B_ * H1];      // [t][b][h1]
__device__ float g_W1T[C_ * H1];                  // [c][h1]
__device__ float g_WrecT[H1 * H1];                // [i][j]
__device__ float g_W2T[H1 * H2];                  // [i][j]
__device__ float g_v1[B_ * H1], g_a1[B_ * H1];
__device__ float g_s1[2][B_ * H1];                // ping-pong spikes layer1
__device__ float g_v2[B_ * H2], g_a2[B_ * H2];
__device__ float g_s2[2][B_ * H2];                // ping-pong spikes layer2
__device__ unsigned g_cnt, g_gen;                 // grid barrier state

// ---------------- f32x2 helpers ------------------------------------------
__device__ __forceinline__ ull pack2(float lo, float hi) {
    ull r; asm("mov.b64 %0, {%1, %2};" : "=l"(r) : "f"(lo), "f"(hi)); return r;
}
__device__ __forceinline__ void fma2(ull& d, ull a, ull b) {
    asm("fma.rn.f32x2 %0, %1, %2, %0;" : "+l"(d) : "l"(a), "l"(b));
}
__device__ __forceinline__ void unpack2(ull v, float& lo, float& hi) {
    asm("mov.b64 {%0, %1}, %2;" : "=f"(lo), "=f"(hi) : "l"(v));
}

// ---------------- software grid barrier -----------------------------------
// epoch is a per-thread-0 register value passed in (monotonic).
__device__ __forceinline__ void grid_sync(unsigned e) {
    __syncthreads();
    __threadfence();   // release: phase writes visible at L2 (+ CCTL.IVALL)
    if (threadIdx.x == 0) {
        unsigned prev = atomicAdd(&g_cnt, 1u);
        if (prev == NB - 1) {
            g_cnt = 0;
            __threadfence();
            atomicExch(&g_gen, e);                       // publish
        } else {
            while (atomicAdd(&g_gen, 0u) < e) {          // L2 read, never cached
                __nanosleep(64);
            }
        }
    }
    __syncthreads();
    __threadfence();   // acquire: CCTL.IVALL -> no stale L1 reads this phase
}

// ---------------- init: zero all state + barrier ---------------------------
__global__ void init_kernel() {
    int i = blockIdx.x * blockDim.x + threadIdx.x;
    int stride = gridDim.x * blockDim.x;
    if (i == 0) { g_cnt = 0; g_gen = 0; }
    for (int k = i; k < B_ * H1; k += stride) {
        g_v1[k] = 0.f; g_a1[k] = 0.f; g_s1[0][k] = 0.f; g_s1[1][k] = 0.f;
    }
    for (int k = i; k < B_ * H2; k += stride) {
        g_v2[k] = 0.f; g_a2[k] = 0.f; g_s2[0][k] = 0.f; g_s2[1][k] = 0.f;
    }
}

// ---------------- transpose weights ----------------------------------------
__global__ void prep_kernel(const float* __restrict__ W1,
                            const float* __restrict__ Wrec,
                            const float* __restrict__ W2) {
    int i = blockIdx.x * blockDim.x + threadIdx.x;
    int stride = gridDim.x * blockDim.x;
    for (int k = i; k < C_ * H1; k += stride) {
        int c = k / H1, h = k % H1;
        g_W1T[k] = W1[h * C_ + c];
    }
    for (int k = i; k < H1 * H1; k += stride) {
        int r = k / H1, j = k % H1;
        g_WrecT[k] = Wrec[j * H1 + r];
    }
    for (int k = i; k < H1 * H2; k += stride) {
        int r = k / H2, j = k % H2;
        g_W2T[k] = W2[j * H1 + r];
    }
}

// ---------------- FF GEMM: g_ff[t*B+b][h] = x[b,t,:] . W1[h,:] -------------
__global__ void __launch_bounds__(256) ff_kernel(const float* __restrict__ x) {
    __shared__ float As[64][17];
    __shared__ float Bs[16][68];
    int tid = threadIdx.x;
    int tx = tid & 15, ty = tid >> 4;
    int n0 = blockIdx.x * 64;
    int row0 = blockIdx.y * 64;

    ull acc[4][2];
#pragma unroll
    for (int m = 0; m < 4; ++m) { acc[m][0] = 0ull; acc[m][1] = 0ull; }

    int am = tid >> 2;
    int ak = (tid & 3) << 2;
    int row = row0 + am;
    int bb = row & 255, tt = row >> 8;
    const float* xr = &x[((size_t)bb * T_ + tt) * C_];
    int bk = tid >> 4;
    int bn = (tid & 15) << 2;

    for (int k0 = 0; k0 < 704; k0 += 16) {
        int kg = k0 + ak;
        float4 av = make_float4(0.f, 0.f, 0.f, 0.f);
        if (kg < C_) av = *(const float4*)&xr[kg];
        int kgb = k0 + bk;
        float4 bv = make_float4(0.f, 0.f, 0.f, 0.f);
        if (kgb < C_) bv = *(const float4*)&g_W1T[(size_t)kgb * H1 + n0 + bn];

        __syncthreads();
        As[am][ak + 0] = av.x; As[am][ak + 1] = av.y;
        As[am][ak + 2] = av.z; As[am][ak + 3] = av.w;
        *(float4*)&Bs[bk][bn] = bv;
        __syncthreads();

#pragma unroll
        for (int k = 0; k < 16; ++k) {
            ull b0 = *(const ull*)&Bs[k][tx * 4];
            ull b1 = *(const ull*)&Bs[k][tx * 4 + 2];
#pragma unroll
            for (int mm = 0; mm < 4; ++mm) {
                float a = As[ty * 4 + mm][k];
                ull ap = pack2(a, a);
                fma2(acc[mm][0], ap, b0);
                fma2(acc[mm][1], ap, b1);
            }
        }
    }
#pragma unroll
    for (int mm = 0; mm < 4; ++mm) {
        size_t rbase = (size_t)(row0 + ty * 4 + mm) * H1 + n0 + tx * 4;
        float v0, v1, v2, v3;
        unpack2(acc[mm][0], v0, v1);
        unpack2(acc[mm][1], v2, v3);
        g_ff[rbase + 0] = v0; g_ff[rbase + 1] = v1;
        g_ff[rbase + 2] = v2; g_ff[rbase + 3] = v3;
    }
}

// ---------------- persistent SNN kernel ------------------------------------
// 148 blocks x 256 threads. Per step:
//   P1: blocks 0..127  : GEMM1 tile 32x64 (I1 = s1(t-1)@WrecT) + neuron1 epilogue
//       blocks 128..143: readout(t-1): I3 = s2(t-1)@W3T, vout/osum in registers
//   barrier
//   P2: blocks 0..127  : GEMM2 tile 32x32 (I2 = s1(t)@W2T) + neuron2 epilogue
//   barrier
__global__ void __launch_bounds__(256, 1) snn_kernel(
    const float* __restrict__ W3,
    const float* __restrict__ alpha1, const float* __restrict__ rho1,
    const float* __restrict__ ba1,
    const float* __restrict__ alpha2, const float* __restrict__ rho2,
    const float* __restrict__ ba2,
    const float* __restrict__ beta_out,
    float* __restrict__ out)
{
    __shared__ float As[32][34];   // [k][m]
    __shared__ float Bs[32][68];   // [k][n]
    const int tid = threadIdx.x;
    const int bx = blockIdx.x;
    unsigned epoch = 0;

    // ---- tile / lane mapping ----
    const int m0  = (bx >> 4) * 32;        // GEMM1+2 m tile (bx<128)
    const int n0  = (bx & 15) * 64;        // GEMM1 n tile
    const int n0b = (bx & 15) * 32;        // GEMM2 n tile
    const int la_m = tid >> 3;             // 0..31  (A loads, both gemms)
    const int la_k = (tid & 7) << 2;       // 0..28
    const int lb_r = tid >> 4;             // 0..15  (GEMM1 B loads)
    const int lb_c = (tid & 15) << 2;      // 0..60
    const int mb   = (tid >> 4) << 1;      // 0..30  (GEMM1 compute, m pair)
    const int nb   = (tid & 15) << 2;      // 0..60  (GEMM1 compute, 4n)
    const int arow = tid >> 3;             // 0..31  (GEMM2 compute row / B load)
    const int nb2  = (tid & 7) << 2;       // 0..28  (GEMM2 compute 4n / B load)

    // ---- hoisted per-thread neuron constants ----
    float4 al1, rh1, bb1, al2, rh2, bb2;
    if (bx < 128) {
        al1 = *(const float4*)&alpha1[n0 + nb];
        rh1 = *(const float4*)&rho1[n0 + nb];
        bb1 = *(const float4*)&ba1[n0 + nb];
        al2 = *(const float4*)&alpha2[n0b + nb2];
        rh2 = *(const float4*)&rho2[n0b + nb2];
        bb2 = *(const float4*)&ba2[n0b + nb2];
    }
    // readout job assignment (blocks 128..143), vout/osum live in registers
    int rb[3], ro[3]; float rbo[3]; int nro = 0;
    float vo[3] = {0.f, 0.f, 0.f}, osum[3] = {0.f, 0.f, 0.f};
    if (bx >= 128 && bx < 144) {
        int base = (bx - 128) * 256 + tid;
        for (int jj = base; jj < B_ * O_; jj += 4096) {
            rb[nro] = jj / O_;
            ro[nro] = jj % O_;
            rbo[nro] = beta_out[jj % O_];
            nro++;
        }
    }

    for (int t = 0; t < T_; ++t) {
        const int par = t & 1;
        const float* __restrict__ s1r = g_s1[par];       // s1(t-1)
        float* __restrict__ s1w = g_s1[par ^ 1];         // s1(t)

        // =================== P1 ===================
        if (bx < 128) {
            ull a00 = 0, a01 = 0, a10 = 0, a11 = 0;
            // prefetch chunk 0
            float4 av  = __ldcg((const float4*)&s1r[(size_t)(m0 + la_m) * H1 + la_k]);
            float4 b0v = __ldg((const float4*)&g_WrecT[(size_t)lb_r * H1 + n0 + lb_c]);
            float4 b1v = __ldg((const float4*)&g_WrecT[(size_t)(lb_r + 16) * H1 + n0 + lb_c]);
            for (int k0 = 0; k0 < H1; k0 += 32) {
                __syncthreads();
                As[la_k + 0][la_m] = av.x;
                As[la_k + 1][la_m] = av.y;
                As[la_k + 2][la_m] = av.z;
                As[la_k + 3][la_m] = av.w;
                *(float4*)&Bs[lb_r][lb_c] = b0v;
                *(float4*)&Bs[lb_r + 16][lb_c] = b1v;
                __syncthreads();
                if (k0 + 32 < H1) {   // prefetch next chunk during compute
                    int kn = k0 + 32;
                    av  = __ldcg((const float4*)&s1r[(size_t)(m0 + la_m) * H1 + kn + la_k]);
                    b0v = __ldg((const float4*)&g_WrecT[(size_t)(kn + lb_r) * H1 + n0 + lb_c]);
                    b1v = __ldg((const float4*)&g_WrecT[(size_t)(kn + lb_r + 16) * H1 + n0 + lb_c]);
                }
#pragma unroll
                for (int k = 0; k < 32; ++k) {
                    ull ap = *(const ull*)&As[k][mb];
                    float x0, x1; unpack2(ap, x0, x1);
                    ull bp0 = *(const ull*)&Bs[k][nb];
                    ull bp1 = *(const ull*)&Bs[k][nb + 2];
                    ull s0 = pack2(x0, x0), s1x = pack2(x1, x1);
                    fma2(a00, s0, bp0);  fma2(a01, s0, bp1);
                    fma2(a10, s1x, bp0); fma2(a11, s1x, bp1);
                }
            }
            // epilogue: neuron1 update for 2 rows x 4 cols
            const size_t ffb = (size_t)t * B_ * H1;
#pragma unroll
            for (int r = 0; r < 2; ++r) {
                int b = m0 + mb + r;
                size_t idx = (size_t)b * H1 + n0 + nb;
                float i0, i1, i2, i3;
                unpack2(r ? a10 : a00, i0, i1);
                unpack2(r ? a11 : a01, i2, i3);
                float4 ffv = __ldg((const float4*)&g_ff[ffb + idx]);
                float4 spv = *(const float4*)&s1r[idx];
                float4 vv  = *(const float4*)&g_v1[idx];
                float4 aa  = *(const float4*)&g_a1[idx];
                float I0 = i0 + ffv.x, I1 = i1 + ffv.y, I2 = i2 + ffv.z, I3 = i3 + ffv.w;
                float vn0 = al1.x * (vv.x - spv.x * THR) + (1.f - al1.x) * (I0 - aa.x);
                float vn1 = al1.y * (vv.y - spv.y * THR) + (1.f - al1.y) * (I1 - aa.y);
                float vn2 = al1.z * (vv.z - spv.z * THR) + (1.f - al1.z) * (I2 - aa.z);
                float vn3 = al1.w * (vv.w - spv.w * THR) + (1.f - al1.w) * (I3 - aa.w);
                float s0 = (vn0 - THR >= 0.f) ? 1.f : 0.f;
                float s1f = (vn1 - THR >= 0.f) ? 1.f : 0.f;
                float s2f = (vn2 - THR >= 0.f) ? 1.f : 0.f;
                float s3 = (vn3 - THR >= 0.f) ? 1.f : 0.f;
                float4 an = make_float4(rh1.x * aa.x + bb1.x * s0,
                                        rh1.y * aa.y + bb1.y * s1f,
                                        rh1.z * aa.z + bb1.z * s2f,
                                        rh1.w * aa.w + bb1.w * s3);
                *(float4*)&g_v1[idx] = make_float4(vn0, vn1, vn2, vn3);
                *(float4*)&g_a1[idx] = an;
                *(float4*)&s1w[idx]  = make_float4(s0, s1f, s2f, s3);
            }
        } else if (bx < 144 && t > 0) {
            // readout for step t-1 : s2(t-1) lives in g_s2[par^1]
            const float* __restrict__ s2r = g_s2[par ^ 1];
            for (int q = 0; q < nro; ++q) {
                const float4* sv = (const float4*)&s2r[rb[q] * H2];
                const float4* wv = (const float4*)&W3[ro[q] * H2];
                float4 acc4 = make_float4(0.f, 0.f, 0.f, 0.f);
#pragma unroll 4
                for (int k = 0; k < H2 / 4; ++k) {
                    float4 s4 = __ldcg(&sv[k]);
                    float4 w4 = __ldg(&wv[k]);
                    acc4.x += s4.x * w4.x; acc4.y += s4.y * w4.y;
                    acc4.z += s4.z * w4.z; acc4.w += s4.w * w4.w;
                }
                float I3 = (acc4.x + acc4.y) + (acc4.z + acc4.w);
                vo[q] = rbo[q] * vo[q] + (1.f - rbo[q]) * I3;
                osum[q] += vo[q];
            }
        }
        grid_sync(++epoch);

        // =================== P2 ===================
        if (bx < 128) {
            const float* __restrict__ s1c = s1w;   // s1(t), from other blocks
            ull c0 = 0, c1 = 0;
            float4 av = __ldcg((const float4*)&s1c[(size_t)(m0 + la_m) * H1 + la_k]);
            float4 bv = __ldg((const float4*)&g_W2T[(size_t)arow * H2 + n0b + nb2]);
            for (int k0 = 0; k0 < H1; k0 += 32) {
                __syncthreads();
                As[la_k + 0][la_m] = av.x;
                As[la_k + 1][la_m] = av.y;
                As[la_k + 2][la_m] = av.z;
                As[la_k + 3][la_m] = av.w;
                *(float4*)&Bs[arow][nb2] = bv;
                __syncthreads();
                if (k0 + 32 < H1) {
                    int kn = k0 + 32;
                    av = __ldcg((const float4*)&s1c[(size_t)(m0 + la_m) * H1 + kn + la_k]);
                    bv = __ldg((const float4*)&g_W2T[(size_t)(kn + arow) * H2 + n0b + nb2]);
                }
#pragma unroll
                for (int k = 0; k < 32; ++k) {
                    float a = As[k][arow];
                    ull asp = pack2(a, a);
                    fma2(c0, asp, *(const ull*)&Bs[k][nb2]);
                    fma2(c1, asp, *(const ull*)&Bs[k][nb2 + 2]);
                }
            }
            // epilogue: neuron2 update (1 row x 4 cols)
            int b = m0 + arow;
            size_t idx = (size_t)b * H2 + n0b + nb2;
            float i0, i1, i2, i3;
            unpack2(c0, i0, i1);
            unpack2(c1, i2, i3);
            const float* __restrict__ s2p = g_s2[par ^ 1];
            float* __restrict__ s2w = g_s2[par];
            float4 spv = *(const float4*)&s2p[idx];
            float4 vv  = *(const float4*)&g_v2[idx];
            float4 aa  = *(const float4*)&g_a2[idx];
            float vn0 = al2.x * (vv.x - spv.x * THR) + (1.f - al2.x) * (i0 - aa.x);
            float vn1 = al2.y * (vv.y - spv.y * THR) + (1.f - al2.y) * (i1 - aa.y);
            float vn2 = al2.z * (vv.z - spv.z * THR) + (1.f - al2.z) * (i2 - aa.z);
            float vn3 = al2.w * (vv.w - spv.w * THR) + (1.f - al2.w) * (i3 - aa.w);
            float s0 = (vn0 - THR >= 0.f) ? 1.f : 0.f;
            float s1f = (vn1 - THR >= 0.f) ? 1.f : 0.f;
            float s2f = (vn2 - THR >= 0.f) ? 1.f : 0.f;
            float s3 = (vn3 - THR >= 0.f) ? 1.f : 0.f;
            float4 an = make_float4(rh2.x * aa.x + bb2.x * s0,
                                    rh2.y * aa.y + bb2.y * s1f,
                                    rh2.z * aa.z + bb2.z * s2f,
                                    rh2.w * aa.w + bb2.w * s3);
            *(float4*)&g_v2[idx] = make_float4(vn0, vn1, vn2, vn3);
            *(float4*)&g_a2[idx] = an;
            *(float4*)&s2w[idx]  = make_float4(s0, s1f, s2f, s3);
        }
        grid_sync(++epoch);
    }

    // ---- final readout for t = 249 + write output ----
    if (bx >= 128 && bx < 144) {
        const float* __restrict__ s2r = g_s2[(T_ - 1) & 1];
        for (int q = 0; q < nro; ++q) {
            const float4* sv = (const float4*)&s2r[rb[q] * H2];
            const float4* wv = (const float4*)&W3[ro[q] * H2];
            float4 acc4 = make_float4(0.f, 0.f, 0.f, 0.f);
#pragma unroll 4
            for (int k = 0; k < H2 / 4; ++k) {
                float4 s4 = __ldcg(&sv[k]);
                float4 w4 = __ldg(&wv[k]);
                acc4.x += s4.x * w4.x; acc4.y += s4.y * w4.y;
                acc4.z += s4.z * w4.z; acc4.w += s4.w * w4.w;
            }
            float I3 = (acc4.x + acc4.y) + (acc4.z + acc4.w);
            vo[q] = rbo[q] * vo[q] + (1.f - rbo[q]) * I3;
            osum[q] += vo[q];
            out[rb[q] * O_ + ro[q]] = osum[q] * (1.0f / (float)T_);
        }
    }
}

// ---------------- launch ---------------------------------------------------
extern "C" void kernel_launch(void* const* d_in, const int* in_sizes, int n_in,
                              void* d_out, int out_size) {
    const float* x      = (const float*)d_in[0];
    const float* W1     = (const float*)d_in[1];
    const float* Wrec   = (const float*)d_in[2];
    const float* W2     = (const float*)d_in[3];
    const float* W3     = (const float*)d_in[4];
    const float* alpha1 = (const float*)d_in[5];
    const float* rho1   = (const float*)d_in[6];
    const float* ba1    = (const float*)d_in[7];
    const float* alpha2 = (const float*)d_in[8];
    const float* rho2   = (const float*)d_in[9];
    const float* ba2    = (const float*)d_in[10];
    const float* bout   = (const float*)d_in[11];
    float* out = (float*)d_out;

    init_kernel<<<1024, 256>>>();
    prep_kernel<<<4096, 256>>>(W1, Wrec, W2);
    ff_kernel<<<dim3(16, 1000), 256>>>(x);
    snn_kernel<<<NB, 256>>>(W3, alpha1, rho1, ba1, alpha2, rho2, ba2, bout, out);
}